// round 5
// baseline (speedup 1.0000x reference)
#include <cuda_runtime.h>
#include <cstdint>
#include <cstddef>

#define Bc 64
#define Sc 512
#define Hc 1024
#define Vc 32000
#define SB (Sc * Bc)

// ---------------- scratch (device globals, no allocation) ----------------
__device__ float g_hWh[Bc * Hc];         // reduced: [b][h] hidden@W_h^T + attn_w_b
__device__ float g_hWhp[4 * Bc * Hc];    // split-K partials
__device__ float g_spart[SB * 32];       // 32 partial scores per row r = s*B+b
__device__ float g_x[Bc * 2 * Hc];       // [b][emb ; context]
__device__ float g_gip[4 * Bc * 3 * Hc]; // gi split-K partials [z][b][3H]
__device__ float g_ghp[4 * Bc * 3 * Hc]; // gh split-K partials [z][b][3H]

// ---------------- portable-PTX helpers ----------------
__device__ __forceinline__ uint32_t smem_u32(const void* p) {
    uint32_t a;
    asm("{ .reg .u64 t; cvta.to.shared.u64 t, %1; cvt.u32.u64 %0, t; }"
        : "=r"(a) : "l"(p));
    return a;
}
#define CPA(dst, src) \
    asm volatile("cp.async.cg.shared.global [%0], [%1], 16;" :: "r"(dst), "l"(src))
#define CPCOMMIT() asm volatile("cp.async.commit_group;" ::: "memory")
#define CPWAIT(n)  asm volatile("cp.async.wait_group %0;" :: "n"(n) : "memory")

__device__ __forceinline__ void mma_tf32(float* c, const uint32_t* a, const uint32_t* b) {
    asm volatile(
        "mma.sync.aligned.m16n8k8.row.col.f32.tf32.tf32.f32 "
        "{%0,%1,%2,%3}, {%4,%5,%6,%7}, {%8,%9}, {%0,%1,%2,%3};"
        : "+f"(c[0]), "+f"(c[1]), "+f"(c[2]), "+f"(c[3])
        : "r"(a[0]), "r"(a[1]), "r"(a[2]), "r"(a[3]), "r"(b[0]), "r"(b[1]));
}
__device__ __forceinline__ void split_tf32(float x, uint32_t& hi, uint32_t& lo) {
    uint32_t h = __float_as_uint(x) & 0xFFFFE000u;
    hi = h;
    lo = __float_as_uint(x - __uint_as_float(h));   // exact (same exponent)
}

// ===========================================================================
// Attention score kernel (mma.sync tf32). CTA tile 128x128, warp tile 64x32,
// K-stage 32, 3-stage circular cp.async pipeline, ONE sync per stage.
//  D[m, n] = enc[m0+m, :] . We[n0+n, :]
//  epilogue: partial[r, col] = sum_{n in warp's 32 cols} tanh(D + hWh[b][n]) * v[n]
// ===========================================================================
__global__ void __launch_bounds__(256, 2)
attn_score_tc(const float* __restrict__ enc, const float* __restrict__ W,
              const float* __restrict__ vvec)
{
    extern __shared__ float sm[];   // 3 stages x (A 128x36 + B 128x36) = 110592 B
    const int tid = threadIdx.x, lane = tid & 31, wid = tid >> 5;
    const int n0 = blockIdx.x * 128, m0 = blockIdx.y * 128;
    const int wm = (wid >> 2) * 64, wn = (wid & 3) * 32;
    const float* Wp = W + Hc;
    const uint32_t sbase = smem_u32(sm);

    float acc[4][4][4] = {};

#define LOAD_STAGE(buf, kk)                                                   \
    do {                                                                      \
        const uint32_t db = sbase + (uint32_t)(buf) * 36864u;                 \
        _Pragma("unroll")                                                     \
        for (int i_ = 0; i_ < 4; i_++) {                                      \
            int c_ = i_ * 256 + tid;                                          \
            int row_ = c_ >> 3, kc_ = c_ & 7;                                 \
            CPA(db + (row_ * 36 + kc_ * 4) * 4,                               \
                enc + (size_t)(m0 + row_) * Hc + (kk) + kc_ * 4);             \
            CPA(db + 18432u + (row_ * 36 + kc_ * 4) * 4,                      \
                Wp + (size_t)(n0 + row_) * (2 * Hc) + (kk) + kc_ * 4);        \
        }                                                                     \
        CPCOMMIT();                                                           \
    } while (0)

    LOAD_STAGE(0, 0);
    LOAD_STAGE(1, 32);
    const int fr = lane >> 2, fc = lane & 3;

    for (int ks = 0; ks < 32; ks++) {
        CPWAIT(1);                      // stage ks resident (own copies)
        __syncthreads();                // all threads' copies visible
        if (ks + 2 < 32) LOAD_STAGE((ks + 2) % 3, (ks + 2) * 32);
        else             CPCOMMIT();    // keep group accounting aligned
        const float* Sa = sm + (ks % 3) * 9216;
        const float* Sb = Sa + 4608;
#pragma unroll
        for (int kh = 0; kh < 4; kh++) {
            const int k8 = kh * 8;
            uint32_t a[4][4], b[4][2];
#pragma unroll
            for (int mi = 0; mi < 4; mi++) {
                const float* ap = Sa + (wm + 16 * mi + fr) * 36 + k8 + fc;
                a[mi][0] = __float_as_uint(ap[0]);
                a[mi][1] = __float_as_uint(ap[288]);
                a[mi][2] = __float_as_uint(ap[4]);
                a[mi][3] = __float_as_uint(ap[292]);
            }
#pragma unroll
            for (int nj = 0; nj < 4; nj++) {
                const float* bp = Sb + (wn + 8 * nj + fr) * 36 + k8 + fc;
                b[nj][0] = __float_as_uint(bp[0]);
                b[nj][1] = __float_as_uint(bp[4]);
            }
#pragma unroll
            for (int mi = 0; mi < 4; mi++)
#pragma unroll
                for (int nj = 0; nj < 4; nj++)
                    mma_tf32(acc[mi][nj], a[mi], b[nj]);
        }
        // no trailing sync: next-iter sync protects the buffer being refilled
    }
#undef LOAD_STAGE
    __syncthreads();   // all warps done with final stages before overlay

    // ---- epilogue: stage hWh slice (stride 133, conflict-free) + v slice ----
    float* shf = sm;
    float* shv = sm + 64 * 133;
    for (int j = tid; j < 64 * 128; j += 256) {
        int b = j >> 7, c = j & 127;
        shf[b * 133 + c] = g_hWh[b * Hc + n0 + c];
    }
    if (tid < 128) shv[tid] = vvec[n0 + tid];
    __syncthreads();

    const int c2 = (lane & 3) * 2;
    float s[4][2] = {};
#pragma unroll
    for (int mi = 0; mi < 4; mi++) {
        const int R0 = wm + 16 * mi + fr;
        const int b0 = R0 & 63, b1 = (R0 + 8) & 63;
#pragma unroll
        for (int nj = 0; nj < 4; nj++) {
            const int n = wn + 8 * nj + c2;
            const float v0 = shv[n], v1 = shv[n + 1];
            s[mi][0] += tanhf(acc[mi][nj][0] + shf[b0 * 133 + n]) * v0
                      + tanhf(acc[mi][nj][1] + shf[b0 * 133 + n + 1]) * v1;
            s[mi][1] += tanhf(acc[mi][nj][2] + shf[b1 * 133 + n]) * v0
                      + tanhf(acc[mi][nj][3] + shf[b1 * 133 + n + 1]) * v1;
        }
    }
#pragma unroll
    for (int mi = 0; mi < 4; mi++)
#pragma unroll
        for (int h = 0; h < 2; h++) {
            s[mi][h] += __shfl_xor_sync(0xffffffffu, s[mi][h], 1);
            s[mi][h] += __shfl_xor_sync(0xffffffffu, s[mi][h], 2);
        }
    if ((lane & 3) == 0) {
        const int col = blockIdx.x * 4 + (wid & 3);
#pragma unroll
        for (int mi = 0; mi < 4; mi++) {
            const int R0 = wm + 16 * mi + fr;
            g_spart[(size_t)(m0 + R0) * 32 + col]     = s[mi][0];
            g_spart[(size_t)(m0 + R0 + 8) * 32 + col] = s[mi][1];
        }
    }
}

// ===========================================================================
// Exact fp32 SIMT split-K GEMM: Cpart[z][n][m] = A[m0+m, zKs:(z+1)Ks] . act[n, ...]
// Tile 64x64, N=64 (batch), grid (M/64, 1, 4).
// ===========================================================================
__global__ void __launch_bounds__(256)
gemm_nt_splitk(const float* __restrict__ A, int lda,
               const float* __restrict__ act, int ldact,
               float* __restrict__ Cpart, int M, int Ks)
{
    __shared__ float As[16][68];
    __shared__ float Bs[16][68];
    const int tid = threadIdx.x;
    const int m0 = blockIdx.x * 64;
    const int z = blockIdx.z;

    const int lrow = tid >> 2, lk = (tid & 3) * 4;
    const float* Ap = A + (size_t)(m0 + lrow) * lda + z * Ks + lk;
    const float* Bp = act + (size_t)lrow * ldact + z * Ks + lk;

    const int ty = tid >> 4, tx = tid & 15;
    float acc[4][4] = {};

    for (int k0 = 0; k0 < Ks; k0 += 16) {
        float4 av = *(const float4*)(Ap + k0);
        float4 bv = *(const float4*)(Bp + k0);
        As[lk + 0][lrow] = av.x; As[lk + 1][lrow] = av.y;
        As[lk + 2][lrow] = av.z; As[lk + 3][lrow] = av.w;
        Bs[lk + 0][lrow] = bv.x; Bs[lk + 1][lrow] = bv.y;
        Bs[lk + 2][lrow] = bv.z; Bs[lk + 3][lrow] = bv.w;
        __syncthreads();
#pragma unroll
        for (int k = 0; k < 16; k++) {
            float4 a = *(const float4*)&As[k][ty * 4];
            float4 b = *(const float4*)&Bs[k][tx * 4];
            float ar[4] = {a.x, a.y, a.z, a.w};
            float br[4] = {b.x, b.y, b.z, b.w};
#pragma unroll
            for (int i = 0; i < 4; i++)
#pragma unroll
                for (int j = 0; j < 4; j++)
                    acc[i][j] += ar[i] * br[j];
        }
        __syncthreads();
    }

#pragma unroll
    for (int i = 0; i < 4; i++)
#pragma unroll
        for (int j = 0; j < 4; j++)
            Cpart[(size_t)(z * 64 + tx * 4 + j) * M + m0 + ty * 4 + i] = acc[i][j];
}

// Reduce hWh partials + attn_w_b -> g_hWh
__global__ void __launch_bounds__(256)
hwh_reduce(const float* __restrict__ awb)
{
    const int idx = blockIdx.x * 256 + threadIdx.x;   // 65536
    const int b = idx >> 10, h = idx & 1023;
    float v = awb[h];
#pragma unroll
    for (int z = 0; z < 4; z++) v += g_hWhp[(size_t)(z * 64 + b) * Hc + h];
    g_hWh[idx] = v;
}

// ===========================================================================
// Logits GEMM: 3-term split-tf32 (near-fp32 accuracy on tensor cores).
//   C[n][m0+m] = sum_k A[m0+m, k] * act[n, k] + bias[m0+m]
// ===========================================================================
__global__ void __launch_bounds__(256)
gemm_wact_tc(const float* __restrict__ A, int lda, int K,
             const float* __restrict__ act,
             float* __restrict__ C, int ldc,
             const float* __restrict__ bias)
{
    __shared__ float sm[7680];   // [2 bufs][ A:128x20 | act:64x20 ]
    const int tid = threadIdx.x, lane = tid & 31, wid = tid >> 5;
    const int m0 = blockIdx.x * 128;
    const int wm = (wid & 3) * 32, wn = (wid >> 2) * 32;

    float acc[2][4][4] = {};

    const int lr = tid >> 2, lc = (tid & 3) * 4;
    const float* Ag0 = A + (size_t)(m0 + lr) * lda + lc;
    const float* Ag1 = A + (size_t)(m0 + lr + 64) * lda + lc;
    const float* Cg  = act + (size_t)lr * K + lc;
    const uint32_t sA0 = smem_u32(&sm[lr * 20 + lc]);
    const uint32_t sA1 = smem_u32(&sm[(lr + 64) * 20 + lc]);
    const uint32_t sC0 = smem_u32(&sm[2560 + lr * 20 + lc]);

#define W_LOAD(buf, k0)                                     \
    do {                                                    \
        CPA(sA0 + (buf) * 15360, Ag0 + (k0));               \
        CPA(sA1 + (buf) * 15360, Ag1 + (k0));               \
        CPA(sC0 + (buf) * 15360, Cg + (k0));                \
        CPCOMMIT();                                         \
    } while (0)

    const int NS = K / 16;
    W_LOAD(0, 0);
    const int fr = lane >> 2, fc = lane & 3;

    for (int ks = 0; ks < NS; ks++) {
        const int buf = ks & 1;
        if (ks + 1 < NS) { W_LOAD(buf ^ 1, (ks + 1) * 16); CPWAIT(1); }
        else             { CPWAIT(0); }
        __syncthreads();
        const float* As = &sm[buf * 3840];
        const float* Bs = &sm[buf * 3840 + 2560];
#pragma unroll
        for (int kh = 0; kh < 2; kh++) {
            const int k8 = kh * 8;
            uint32_t ah[2][4], al[2][4], bh[4][2], bl[4][2];
#pragma unroll
            for (int mi = 0; mi < 2; mi++) {
                const float* ap = As + (wm + 16 * mi + fr) * 20 + k8 + fc;
                split_tf32(ap[0],   ah[mi][0], al[mi][0]);
                split_tf32(ap[160], ah[mi][1], al[mi][1]);
                split_tf32(ap[4],   ah[mi][2], al[mi][2]);
                split_tf32(ap[164], ah[mi][3], al[mi][3]);
            }
#pragma unroll
            for (int nj = 0; nj < 4; nj++) {
                const float* bp = Bs + (wn + 8 * nj + fr) * 20 + k8 + fc;
                split_tf32(bp[0], bh[nj][0], bl[nj][0]);
                split_tf32(bp[4], bh[nj][1], bl[nj][1]);
            }
#pragma unroll
            for (int mi = 0; mi < 2; mi++)
#pragma unroll
                for (int nj = 0; nj < 4; nj++) {
                    mma_tf32(acc[mi][nj], ah[mi], bl[nj]);
                    mma_tf32(acc[mi][nj], al[mi], bh[nj]);
                    mma_tf32(acc[mi][nj], ah[mi], bh[nj]);
                }
        }
        __syncthreads();
    }
#undef W_LOAD

    const int c2 = (lane & 3) * 2;
#pragma unroll
    for (int mi = 0; mi < 2; mi++) {
        const int m = m0 + wm + 16 * mi + fr;
        const float bm0 = bias[m], bm1 = bias[m + 8];
#pragma unroll
        for (int nj = 0; nj < 4; nj++) {
            const int n = wn + 8 * nj + c2;
            C[(size_t)n * ldc + m]           = acc[mi][nj][0] + bm0;
            C[(size_t)(n + 1) * ldc + m]     = acc[mi][nj][1] + bm0;
            C[(size_t)n * ldc + m + 8]       = acc[mi][nj][2] + bm1;
            C[(size_t)(n + 1) * ldc + m + 8] = acc[mi][nj][3] + bm1;
        }
    }
}

// ===========================================================================
// Softmax over seq (512) per batch. Sums the 32 attention partials.
// ===========================================================================
__global__ void __launch_bounds__(256)
softmax_kernel(float* __restrict__ wout)
{
    __shared__ float sc[Sc];
    __shared__ float red[256];
    const int b = blockIdx.x, tid = threadIdx.x;

    for (int s = tid; s < Sc; s += 256) {
        const float4* p = (const float4*)&g_spart[(size_t)(s * Bc + b) * 32];
        float v = 0.0f;
#pragma unroll
        for (int i = 0; i < 8; i++) {
            float4 q = p[i];
            v += q.x + q.y + q.z + q.w;
        }
        sc[s] = v;
    }
    __syncthreads();

    float m = fmaxf(sc[tid], sc[tid + 256]);
    red[tid] = m;
    __syncthreads();
    for (int st = 128; st > 0; st >>= 1) {
        if (tid < st) red[tid] = fmaxf(red[tid], red[tid + st]);
        __syncthreads();
    }
    float mx = red[0];
    __syncthreads();

    float e0 = expf(sc[tid] - mx);
    float e1 = expf(sc[tid + 256] - mx);
    sc[tid] = e0; sc[tid + 256] = e1;
    red[tid] = e0 + e1;
    __syncthreads();
    for (int st = 128; st > 0; st >>= 1) {
        if (tid < st) red[tid] += red[tid + st];
        __syncthreads();
    }
    float inv = 1.0f / red[0];

    wout[(size_t)tid * Bc + b]         = sc[tid] * inv;
    wout[(size_t)(tid + 256) * Bc + b] = sc[tid + 256] * inv;
}

__global__ void __launch_bounds__(256)
embed_kernel(const int* __restrict__ input, const float* __restrict__ emb)
{
    const int b = blockIdx.x;
    const int idx = input[b];
    const float4* src = (const float4*)(emb + (size_t)idx * Hc);
    float4* dst = (float4*)(g_x + (size_t)b * 2 * Hc);
    dst[threadIdx.x] = src[threadIdx.x];
}

__global__ void __launch_bounds__(256)
context_kernel(const float* __restrict__ enc, const float* __restrict__ wts)
{
    __shared__ float w[Sc];
    const int kc = blockIdx.x, b = blockIdx.y, tid = threadIdx.x;
    w[tid]       = wts[(size_t)tid * Bc + b];
    w[tid + 256] = wts[(size_t)(tid + 256) * Bc + b];
    __syncthreads();

    const int k = kc * 256 + tid;
    const float* p = enc + (size_t)b * Hc + k;
    float acc = 0.0f;
#pragma unroll 8
    for (int s = 0; s < Sc; s++)
        acc += w[s] * p[(size_t)s * (Bc * Hc)];
    g_x[(size_t)b * 2 * Hc + Hc + k] = acc;
}

// GRU gate combine: sums the 4 split-K partials of gi/gh inline (exact fp32).
__global__ void __launch_bounds__(256)
gru_kernel(const float* __restrict__ hidden, float* __restrict__ hnew,
           const float* __restrict__ bih, const float* __restrict__ bhh)
{
    const int g = blockIdx.x * 256 + threadIdx.x;   // 65536
    const int b = g >> 10, h = g & 1023;

    float gir = bih[h],            ghr = bhh[h];
    float giz = bih[Hc + h],       ghz = bhh[Hc + h];
    float gin = bih[2 * Hc + h],   ghn = bhh[2 * Hc + h];
#pragma unroll
    for (int z = 0; z < 4; z++) {
        const float* gi = g_gip + (size_t)(z * 64 + b) * (3 * Hc);
        const float* gh = g_ghp + (size_t)(z * 64 + b) * (3 * Hc);
        gir += gi[h];          ghr += gh[h];
        giz += gi[Hc + h];     ghz += gh[Hc + h];
        gin += gi[2 * Hc + h]; ghn += gh[2 * Hc + h];
    }
    float r = 1.0f / (1.0f + expf(-(gir + ghr)));
    float z = 1.0f / (1.0f + expf(-(giz + ghz)));
    float n = tanhf(gin + r * ghn);
    float hp = hidden[g];
    hnew[g] = (1.0f - z) * n + z * hp;
}

// ===========================================================================
extern "C" void kernel_launch(void* const* d_in, const int* in_sizes, int n_in,
                              void* d_out, int out_size)
{
    const int*   input    = (const int*)d_in[0];
    const float* hidden   = (const float*)d_in[1];
    const float* enc      = (const float*)d_in[2];
    const float* emb      = (const float*)d_in[3];
    const float* attn_w_W = (const float*)d_in[4];
    const float* attn_w_b = (const float*)d_in[5];
    const float* attn_v_W = (const float*)d_in[6];
    // d_in[7] = attn_v_b : softmax-invariant, skipped
    const float* gru_Wih  = (const float*)d_in[8];
    const float* gru_Whh  = (const float*)d_in[9];
    const float* gru_bih  = (const float*)d_in[10];
    const float* gru_bhh  = (const float*)d_in[11];
    const float* out_W    = (const float*)d_in[12];
    const float* out_b    = (const float*)d_in[13];

    float* out    = (float*)d_out;
    float* logits = out;                        // B*V
    float* hnew   = out + (size_t)Bc * Vc;      // B*H
    float* wts    = hnew + (size_t)Bc * Hc;     // S*B

    float *p_hWhp, *p_gx, *p_gip, *p_ghp;
    cudaGetSymbolAddress((void**)&p_hWhp, g_hWhp);
    cudaGetSymbolAddress((void**)&p_gx,   g_x);
    cudaGetSymbolAddress((void**)&p_gip,  g_gip);
    cudaGetSymbolAddress((void**)&p_ghp,  g_ghp);

    cudaFuncSetAttribute(attn_score_tc, cudaFuncAttributeMaxDynamicSharedMemorySize, 110592);

    // 1. hWh split-K partials (exact fp32): W_h = attn_w_W[:, 0:H]
    gemm_nt_splitk<<<dim3(16, 1, 4), 256>>>(attn_w_W, 2 * Hc, hidden, Hc, p_hWhp, Hc, 256);
    // 2. reduce + bias -> g_hWh
    hwh_reduce<<<256, 256>>>(attn_w_b);
    // 3. gh split-K partials (exact fp32), independent of attention
    gemm_nt_splitk<<<dim3(48, 1, 4), 256>>>(gru_Whh, Hc, hidden, Hc, p_ghp, 3 * Hc, 256);
    // 4. fused attention scores (tf32 tensor + tanh + v-dot)   [profiled slot]
    attn_score_tc<<<dim3(8, 256), 256, 110592>>>(enc, attn_w_W, attn_v_W);
    // 5. softmax over seq -> attn_weights (output region 3)
    softmax_kernel<<<Bc, 256>>>(wts);
    // 6. embedding gather
    embed_kernel<<<Bc, 256>>>(input, emb);
    // 7. context (exact fp32)
    context_kernel<<<dim3(4, Bc), 256>>>(enc, wts);
    // 8. gi split-K partials (exact fp32)
    gemm_nt_splitk<<<dim3(48, 1, 4), 256>>>(gru_Wih, 2 * Hc, p_gx, 2 * Hc, p_gip, 3 * Hc, 512);
    // 9. GRU combine (sums partials) -> h_new (output region 2)
    gru_kernel<<<Bc * Hc / 256, 256>>>(hidden, hnew, gru_bih, gru_bhh);
    // 10. logits = h_new @ out_W^T + out_b (3-term split-tf32, output region 1)
    gemm_wact_tc<<<Vc / 128, 256>>>(out_W, Hc, Hc, hnew, logits, Vc, out_b);
}

// round 6
// speedup vs baseline: 1.5120x; 1.5120x over previous
#include <cuda_runtime.h>
#include <cstdint>
#include <cstddef>

#define Bc 64
#define Sc 512
#define Hc 1024
#define Vc 32000
#define SB (Sc * Bc)

// ---------------- scratch (device globals, no allocation) ----------------
__device__ float g_hWh[Bc * Hc];         // reduced: [b][h] hidden@W_h^T + attn_w_b
__device__ float g_hWhp[4 * Bc * Hc];    // split-K partials
__device__ float g_spart[SB * 32];       // 32 partial scores per row r = s*B+b
__device__ float g_x[Bc * 2 * Hc];       // [b][emb ; context]
__device__ float g_gip[4 * Bc * 3 * Hc]; // gi split-K partials [z][b][3H]
__device__ float g_ghp[4 * Bc * 3 * Hc]; // gh split-K partials [z][b][3H]

// ---------------- portable-PTX helpers ----------------
__device__ __forceinline__ uint32_t smem_u32(const void* p) {
    uint32_t a;
    asm("{ .reg .u64 t; cvta.to.shared.u64 t, %1; cvt.u32.u64 %0, t; }"
        : "=r"(a) : "l"(p));
    return a;
}
#define CPA(dst, src) \
    asm volatile("cp.async.cg.shared.global [%0], [%1], 16;" :: "r"(dst), "l"(src))
#define CPCOMMIT() asm volatile("cp.async.commit_group;" ::: "memory")
#define CPWAIT(n)  asm volatile("cp.async.wait_group %0;" :: "n"(n) : "memory")

__device__ __forceinline__ void mma_tf32(float* c, const uint32_t* a, const uint32_t* b) {
    asm volatile(
        "mma.sync.aligned.m16n8k8.row.col.f32.tf32.tf32.f32 "
        "{%0,%1,%2,%3}, {%4,%5,%6,%7}, {%8,%9}, {%0,%1,%2,%3};"
        : "+f"(c[0]), "+f"(c[1]), "+f"(c[2]), "+f"(c[3])
        : "r"(a[0]), "r"(a[1]), "r"(a[2]), "r"(a[3]), "r"(b[0]), "r"(b[1]));
}
__device__ __forceinline__ void split_tf32(float x, uint32_t& hi, uint32_t& lo) {
    uint32_t h = __float_as_uint(x) & 0xFFFFE000u;
    hi = h;
    lo = __float_as_uint(x - __uint_as_float(h));   // exact (same exponent)
}

// ===========================================================================
// Attention score kernel (mma.sync tf32). CTA tile 128x128, warp tile 64x32,
// K-stage 32, 2-stage double buffer (static addressing), 2 CTAs/SM.
// hWh/v epilogue operands prefetched via cp.async into a 3rd smem region,
// merged into the first pipeline group (hidden under the mainloop).
// ===========================================================================
// smem: stage0 36864 | stage1 36864 | hWh 64x136 fl (34816 B) | v 128 fl (512 B)
#define ATT_SMEM 109056

__global__ void __launch_bounds__(256, 2)
attn_score_tc(const float* __restrict__ enc, const float* __restrict__ W,
              const float* __restrict__ vvec)
{
    extern __shared__ float sm[];
    const int tid = threadIdx.x, lane = tid & 31, wid = tid >> 5;
    const int n0 = blockIdx.x * 128, m0 = blockIdx.y * 128;
    const int wm = (wid >> 2) * 64, wn = (wid & 3) * 32;
    const float* Wp = W + Hc;
    const uint32_t sbase = smem_u32(sm);

    float acc[4][4][4] = {};

#define LOAD_STAGE(buf, kk)                                                   \
    do {                                                                      \
        const uint32_t db = sbase + (buf) * 36864u;                           \
        _Pragma("unroll")                                                     \
        for (int i_ = 0; i_ < 4; i_++) {                                      \
            int c_ = i_ * 256 + tid;                                          \
            int row_ = c_ >> 3, kc_ = c_ & 7;                                 \
            CPA(db + (row_ * 36 + kc_ * 4) * 4,                               \
                enc + (size_t)(m0 + row_) * Hc + (kk) + kc_ * 4);             \
            CPA(db + 18432u + (row_ * 36 + kc_ * 4) * 4,                      \
                Wp + (size_t)(n0 + row_) * (2 * Hc) + (kk) + kc_ * 4);        \
        }                                                                     \
        CPCOMMIT();                                                           \
    } while (0)

    // ---- epilogue-operand prefetch (joins the first commit group) ----
    {
        const uint32_t hbase = sbase + 73728u;
#pragma unroll
        for (int i = 0; i < 8; i++) {
            int j = i * 256 + tid;             // 0..2047
            int row = j >> 5, seg = j & 31;    // 64 rows x 32 16B-segs
            CPA(hbase + (uint32_t)(row * 544 + seg * 16),
                g_hWh + (size_t)row * Hc + n0 + seg * 4);
        }
        if (tid < 32)
            CPA(hbase + 34816u + tid * 16, vvec + n0 + tid * 4);
    }
    LOAD_STAGE(0, 0);
    const int fr = lane >> 2, fc = lane & 3;

    for (int ks = 0; ks < 32; ks++) {
        const int buf = ks & 1;
        if (ks < 31) { LOAD_STAGE(buf ^ 1, (ks + 1) * 32); CPWAIT(1); }
        else         { CPWAIT(0); }
        __syncthreads();
        const float* Sa = sm + buf * 9216;
        const float* Sb = Sa + 4608;
#pragma unroll
        for (int kh = 0; kh < 4; kh++) {
            const int k8 = kh * 8;
            uint32_t a[4][4], b[4][2];
#pragma unroll
            for (int mi = 0; mi < 4; mi++) {
                const float* ap = Sa + (wm + 16 * mi + fr) * 36 + k8 + fc;
                a[mi][0] = __float_as_uint(ap[0]);
                a[mi][1] = __float_as_uint(ap[288]);
                a[mi][2] = __float_as_uint(ap[4]);
                a[mi][3] = __float_as_uint(ap[292]);
            }
#pragma unroll
            for (int nj = 0; nj < 4; nj++) {
                const float* bp = Sb + (wn + 8 * nj + fr) * 36 + k8 + fc;
                b[nj][0] = __float_as_uint(bp[0]);
                b[nj][1] = __float_as_uint(bp[4]);
            }
#pragma unroll
            for (int mi = 0; mi < 4; mi++)
#pragma unroll
                for (int nj = 0; nj < 4; nj++)
                    mma_tf32(acc[mi][nj], a[mi], b[nj]);
        }
        __syncthreads();
    }
#undef LOAD_STAGE

    // ---- epilogue: hWh (stride 136) and v already resident in smem ----
    const float* shf = sm + 18432;
    const float* shv = sm + 27136;

    const int c2 = (lane & 3) * 2;
    float s[4][2] = {};
#pragma unroll
    for (int mi = 0; mi < 4; mi++) {
        const int R0 = wm + 16 * mi + fr;
        const int b0 = R0 & 63, b1 = (R0 + 8) & 63;
#pragma unroll
        for (int nj = 0; nj < 4; nj++) {
            const int n = wn + 8 * nj + c2;
            const float v0 = shv[n], v1 = shv[n + 1];
            s[mi][0] += tanhf(acc[mi][nj][0] + shf[b0 * 136 + n]) * v0
                      + tanhf(acc[mi][nj][1] + shf[b0 * 136 + n + 1]) * v1;
            s[mi][1] += tanhf(acc[mi][nj][2] + shf[b1 * 136 + n]) * v0
                      + tanhf(acc[mi][nj][3] + shf[b1 * 136 + n + 1]) * v1;
        }
    }
#pragma unroll
    for (int mi = 0; mi < 4; mi++)
#pragma unroll
        for (int h = 0; h < 2; h++) {
            s[mi][h] += __shfl_xor_sync(0xffffffffu, s[mi][h], 1);
            s[mi][h] += __shfl_xor_sync(0xffffffffu, s[mi][h], 2);
        }
    if ((lane & 3) == 0) {
        const int col = blockIdx.x * 4 + (wid & 3);
#pragma unroll
        for (int mi = 0; mi < 4; mi++) {
            const int R0 = wm + 16 * mi + fr;
            g_spart[(size_t)(m0 + R0) * 32 + col]     = s[mi][0];
            g_spart[(size_t)(m0 + R0 + 8) * 32 + col] = s[mi][1];
        }
    }
}

// ===========================================================================
// Exact fp32 SIMT split-K GEMM: Cpart[z][n][m] = A[m0+m, zKs:(z+1)Ks] . act[n, ...]
// ===========================================================================
__global__ void __launch_bounds__(256)
gemm_nt_splitk(const float* __restrict__ A, int lda,
               const float* __restrict__ act, int ldact,
               float* __restrict__ Cpart, int M, int Ks)
{
    __shared__ float As[16][68];
    __shared__ float Bs[16][68];
    const int tid = threadIdx.x;
    const int m0 = blockIdx.x * 64;
    const int z = blockIdx.z;

    const int lrow = tid >> 2, lk = (tid & 3) * 4;
    const float* Ap = A + (size_t)(m0 + lrow) * lda + z * Ks + lk;
    const float* Bp = act + (size_t)lrow * ldact + z * Ks + lk;

    const int ty = tid >> 4, tx = tid & 15;
    float acc[4][4] = {};

    for (int k0 = 0; k0 < Ks; k0 += 16) {
        float4 av = *(const float4*)(Ap + k0);
        float4 bv = *(const float4*)(Bp + k0);
        As[lk + 0][lrow] = av.x; As[lk + 1][lrow] = av.y;
        As[lk + 2][lrow] = av.z; As[lk + 3][lrow] = av.w;
        Bs[lk + 0][lrow] = bv.x; Bs[lk + 1][lrow] = bv.y;
        Bs[lk + 2][lrow] = bv.z; Bs[lk + 3][lrow] = bv.w;
        __syncthreads();
#pragma unroll
        for (int k = 0; k < 16; k++) {
            float4 a = *(const float4*)&As[k][ty * 4];
            float4 b = *(const float4*)&Bs[k][tx * 4];
            float ar[4] = {a.x, a.y, a.z, a.w};
            float br[4] = {b.x, b.y, b.z, b.w};
#pragma unroll
            for (int i = 0; i < 4; i++)
#pragma unroll
                for (int j = 0; j < 4; j++)
                    acc[i][j] += ar[i] * br[j];
        }
        __syncthreads();
    }

#pragma unroll
    for (int i = 0; i < 4; i++)
#pragma unroll
        for (int j = 0; j < 4; j++)
            Cpart[(size_t)(z * 64 + tx * 4 + j) * M + m0 + ty * 4 + i] = acc[i][j];
}

// Reduce hWh partials + attn_w_b -> g_hWh
__global__ void __launch_bounds__(256)
hwh_reduce(const float* __restrict__ awb)
{
    const int idx = blockIdx.x * 256 + threadIdx.x;   // 65536
    const int b = idx >> 10, h = idx & 1023;
    float v = awb[h];
#pragma unroll
    for (int z = 0; z < 4; z++) v += g_hWhp[(size_t)(z * 64 + b) * Hc + h];
    g_hWh[idx] = v;
}

// ===========================================================================
// Logits GEMM: 3-term split-tf32 (near-fp32 accuracy on tensor cores).
// ===========================================================================
__global__ void __launch_bounds__(256)
gemm_wact_tc(const float* __restrict__ A, int lda, int K,
             const float* __restrict__ act,
             float* __restrict__ C, int ldc,
             const float* __restrict__ bias)
{
    __shared__ float sm[7680];   // [2 bufs][ A:128x20 | act:64x20 ]
    const int tid = threadIdx.x, lane = tid & 31, wid = tid >> 5;
    const int m0 = blockIdx.x * 128;
    const int wm = (wid & 3) * 32, wn = (wid >> 2) * 32;

    float acc[2][4][4] = {};

    const int lr = tid >> 2, lc = (tid & 3) * 4;
    const float* Ag0 = A + (size_t)(m0 + lr) * lda + lc;
    const float* Ag1 = A + (size_t)(m0 + lr + 64) * lda + lc;
    const float* Cg  = act + (size_t)lr * K + lc;
    const uint32_t sA0 = smem_u32(&sm[lr * 20 + lc]);
    const uint32_t sA1 = smem_u32(&sm[(lr + 64) * 20 + lc]);
    const uint32_t sC0 = smem_u32(&sm[2560 + lr * 20 + lc]);

#define W_LOAD(buf, k0)                                     \
    do {                                                    \
        CPA(sA0 + (buf) * 15360, Ag0 + (k0));               \
        CPA(sA1 + (buf) * 15360, Ag1 + (k0));               \
        CPA(sC0 + (buf) * 15360, Cg + (k0));                \
        CPCOMMIT();                                         \
    } while (0)

    const int NS = K / 16;
    W_LOAD(0, 0);
    const int fr = lane >> 2, fc = lane & 3;

    for (int ks = 0; ks < NS; ks++) {
        const int buf = ks & 1;
        if (ks + 1 < NS) { W_LOAD(buf ^ 1, (ks + 1) * 16); CPWAIT(1); }
        else             { CPWAIT(0); }
        __syncthreads();
        const float* As = &sm[buf * 3840];
        const float* Bs = &sm[buf * 3840 + 2560];
#pragma unroll
        for (int kh = 0; kh < 2; kh++) {
            const int k8 = kh * 8;
            uint32_t ah[2][4], al[2][4], bh[4][2], bl[4][2];
#pragma unroll
            for (int mi = 0; mi < 2; mi++) {
                const float* ap = As + (wm + 16 * mi + fr) * 20 + k8 + fc;
                split_tf32(ap[0],   ah[mi][0], al[mi][0]);
                split_tf32(ap[160], ah[mi][1], al[mi][1]);
                split_tf32(ap[4],   ah[mi][2], al[mi][2]);
                split_tf32(ap[164], ah[mi][3], al[mi][3]);
            }
#pragma unroll
            for (int nj = 0; nj < 4; nj++) {
                const float* bp = Bs + (wn + 8 * nj + fr) * 20 + k8 + fc;
                split_tf32(bp[0], bh[nj][0], bl[nj][0]);
                split_tf32(bp[4], bh[nj][1], bl[nj][1]);
            }
#pragma unroll
            for (int mi = 0; mi < 2; mi++)
#pragma unroll
                for (int nj = 0; nj < 4; nj++) {
                    mma_tf32(acc[mi][nj], ah[mi], bl[nj]);
                    mma_tf32(acc[mi][nj], al[mi], bh[nj]);
                    mma_tf32(acc[mi][nj], ah[mi], bh[nj]);
                }
        }
        __syncthreads();
    }
#undef W_LOAD

    const int c2 = (lane & 3) * 2;
#pragma unroll
    for (int mi = 0; mi < 2; mi++) {
        const int m = m0 + wm + 16 * mi + fr;
        const float bm0 = bias[m], bm1 = bias[m + 8];
#pragma unroll
        for (int nj = 0; nj < 4; nj++) {
            const int n = wn + 8 * nj + c2;
            C[(size_t)n * ldc + m]           = acc[mi][nj][0] + bm0;
            C[(size_t)(n + 1) * ldc + m]     = acc[mi][nj][1] + bm0;
            C[(size_t)n * ldc + m + 8]       = acc[mi][nj][2] + bm1;
            C[(size_t)(n + 1) * ldc + m + 8] = acc[mi][nj][3] + bm1;
        }
    }
}

// ===========================================================================
// Fused: per-b softmax (local recompute) + attn_weights write (kc==0) +
// embedding copy + context. grid (4 k-chunks, 64 b).
// ===========================================================================
__global__ void __launch_bounds__(256)
ctx_fused(const float* __restrict__ enc, const int* __restrict__ input,
          const float* __restrict__ emb, float* __restrict__ wout)
{
    __shared__ float sc[Sc];
    __shared__ float red[256];
    const int kc = blockIdx.x, b = blockIdx.y, tid = threadIdx.x;

    for (int s = tid; s < Sc; s += 256) {
        const float4* p = (const float4*)&g_spart[(size_t)(s * Bc + b) * 32];
        float v = 0.0f;
#pragma unroll
        for (int i = 0; i < 8; i++) {
            float4 q = p[i];
            v += q.x + q.y + q.z + q.w;
        }
        sc[s] = v;
    }
    __syncthreads();

    float m = fmaxf(sc[tid], sc[tid + 256]);
    red[tid] = m;
    __syncthreads();
    for (int st = 128; st > 0; st >>= 1) {
        if (tid < st) red[tid] = fmaxf(red[tid], red[tid + st]);
        __syncthreads();
    }
    float mx = red[0];
    __syncthreads();

    float e0 = expf(sc[tid] - mx);
    float e1 = expf(sc[tid + 256] - mx);
    red[tid] = e0 + e1;
    __syncthreads();
    for (int st = 128; st > 0; st >>= 1) {
        if (tid < st) red[tid] += red[tid + st];
        __syncthreads();
    }
    float inv = 1.0f / red[0];
    sc[tid]       = e0 * inv;
    sc[tid + 256] = e1 * inv;
    __syncthreads();

    if (kc == 0) {   // attn_weights output (region 3)
        wout[(size_t)tid * Bc + b]         = sc[tid];
        wout[(size_t)(tid + 256) * Bc + b] = sc[tid + 256];
    }

    // embedding copy for this k-chunk
    const int idx = input[b];
    const int k = kc * 256 + tid;
    g_x[(size_t)b * 2 * Hc + k] = emb[(size_t)idx * Hc + k];

    // context
    const float* p = enc + (size_t)b * Hc + k;
    float acc = 0.0f;
#pragma unroll 8
    for (int s = 0; s < Sc; s++)
        acc += sc[s] * p[(size_t)s * (Bc * Hc)];
    g_x[(size_t)b * 2 * Hc + Hc + k] = acc;
}

// GRU gate combine: sums the 4 split-K partials of gi/gh inline (exact fp32).
__global__ void __launch_bounds__(256)
gru_kernel(const float* __restrict__ hidden, float* __restrict__ hnew,
           const float* __restrict__ bih, const float* __restrict__ bhh)
{
    const int g = blockIdx.x * 256 + threadIdx.x;   // 65536
    const int b = g >> 10, h = g & 1023;

    float gir = bih[h],            ghr = bhh[h];
    float giz = bih[Hc + h],       ghz = bhh[Hc + h];
    float gin = bih[2 * Hc + h],   ghn = bhh[2 * Hc + h];
#pragma unroll
    for (int z = 0; z < 4; z++) {
        const float* gi = g_gip + (size_t)(z * 64 + b) * (3 * Hc);
        const float* gh = g_ghp + (size_t)(z * 64 + b) * (3 * Hc);
        gir += gi[h];          ghr += gh[h];
        giz += gi[Hc + h];     ghz += gh[Hc + h];
        gin += gi[2 * Hc + h]; ghn += gh[2 * Hc + h];
    }
    float r = 1.0f / (1.0f + expf(-(gir + ghr)));
    float z = 1.0f / (1.0f + expf(-(giz + ghz)));
    float n = tanhf(gin + r * ghn);
    float hp = hidden[g];
    hnew[g] = (1.0f - z) * n + z * hp;
}

// ===========================================================================
extern "C" void kernel_launch(void* const* d_in, const int* in_sizes, int n_in,
                              void* d_out, int out_size)
{
    const int*   input    = (const int*)d_in[0];
    const float* hidden   = (const float*)d_in[1];
    const float* enc      = (const float*)d_in[2];
    const float* emb      = (const float*)d_in[3];
    const float* attn_w_W = (const float*)d_in[4];
    const float* attn_w_b = (const float*)d_in[5];
    const float* attn_v_W = (const float*)d_in[6];
    // d_in[7] = attn_v_b : softmax-invariant, skipped
    const float* gru_Wih  = (const float*)d_in[8];
    const float* gru_Whh  = (const float*)d_in[9];
    const float* gru_bih  = (const float*)d_in[10];
    const float* gru_bhh  = (const float*)d_in[11];
    const float* out_W    = (const float*)d_in[12];
    const float* out_b    = (const float*)d_in[13];

    float* out    = (float*)d_out;
    float* logits = out;                        // B*V
    float* hnew   = out + (size_t)Bc * Vc;      // B*H
    float* wts    = hnew + (size_t)Bc * Hc;     // S*B

    float *p_hWhp, *p_gx, *p_gip, *p_ghp;
    cudaGetSymbolAddress((void**)&p_hWhp, g_hWhp);
    cudaGetSymbolAddress((void**)&p_gx,   g_x);
    cudaGetSymbolAddress((void**)&p_gip,  g_gip);
    cudaGetSymbolAddress((void**)&p_ghp,  g_ghp);

    cudaFuncSetAttribute(attn_score_tc, cudaFuncAttributeMaxDynamicSharedMemorySize, ATT_SMEM);

    // 1. hWh split-K partials (exact fp32): W_h = attn_w_W[:, 0:H]
    gemm_nt_splitk<<<dim3(16, 1, 4), 256>>>(attn_w_W, 2 * Hc, hidden, Hc, p_hWhp, Hc, 256);
    // 2. reduce + bias -> g_hWh
    hwh_reduce<<<256, 256>>>(attn_w_b);
    // 3. gh split-K partials (exact fp32), independent of attention
    gemm_nt_splitk<<<dim3(48, 1, 4), 256>>>(gru_Whh, Hc, hidden, Hc, p_ghp, 3 * Hc, 256);
    // 4. fused attention scores (tf32 tensor + tanh + v-dot)   [profiled slot]
    attn_score_tc<<<dim3(8, 256), 256, ATT_SMEM>>>(enc, attn_w_W, attn_v_W);
    // 5. fused softmax + attn_weights + embed + context
    ctx_fused<<<dim3(4, Bc), 256>>>(enc, input, emb, wts);
    // 6. gi split-K partials (exact fp32)
    gemm_nt_splitk<<<dim3(48, 1, 4), 256>>>(gru_Wih, 2 * Hc, p_gx, 2 * Hc, p_gip, 3 * Hc, 512);
    // 7. GRU combine (sums partials) -> h_new (output region 2)
    gru_kernel<<<Bc * Hc / 256, 256>>>(hidden, hnew, gru_bih, gru_bhh);
    // 8. logits = h_new @ out_W^T + out_b (3-term split-tf32, output region 1)
    gemm_wact_tc<<<Vc / 128, 256>>>(out_W, Hc, Hc, hnew, logits, Vc, out_b);
}